// round 7
// baseline (speedup 1.0000x reference)
#include <cuda_runtime.h>
#include <cuda_fp16.h>
#include <math.h>
#include <stdint.h>

// Problem constants
#define BB   256
#define TT   256
#define II   256
#define HH   1024
#define KTOT 1280
#define NG   4096
#define TAUc 0.05f
#define MHUc 1.5f
#define BTH  ((long)BB * TT * HH)
#define BH   ((long)BB * HH)

// Tiling: BM=64, BN=64, stage BK=64 (4 x k16). Grid (64 ctan, 4 mtile) = 256 CTAs,
// 2 CTAs/SM. 256 threads = 8 warps, 4 m-warps x 2 n-warps, warp tile 16x32.
#define NKT    40          // 32-k images (KTOT/32)
#define XKT    8           // x images per (t, mt128)
#define NST    20          // stages per step (KTOT/64)
#define XST    4           // x stages
#define STAGES 4
#define A_IMG  2048        // uint32 per 32-k A image (128 rows x 32 k fp16)
#define B_IMG  1024        // uint32 per 32-k B image (64 n x 32 k fp16)
// per-CTA stage: A 8KB (512 uint4 = 2 half-images), B 8KB
#define DSMEM  (STAGES * 1024 * 16)   // 64KB dynamic smem

// ---------------------------------------------------------------------------
// Persistent scratch: operand images stored exactly as smem stages should look
// (mma-fragment register images, fp16) -> per-step copies are pure linear.
// A image: [mb(8)][kb16(2)][lane(32)][reg(4)] uint32 (128 rows x 32 k):
//   reg j, half h: row' = (lane>>2) + 8*(j&1), k' = (lane&3)*2 + 8*(j>>1) + h
// B image: [nbp(4)][kb16(2)][lane(32)][j(4)] uint32:
//   nb = nbp*2 + (j>>1), r = j&1: k = r*8 + (lane&3)*2 + h, n = nb*8 + (lane>>2)
// ---------------------------------------------------------------------------
__device__ uint32_t g_xp[(long)TT * 2 * XKT * A_IMG];
__device__ uint32_t g_hp[2][2 * 32 * A_IMG];
__device__ uint32_t g_Wp[(long)64 * NKT * B_IMG];
__device__ float    g_c[BB * HH];

__device__ __forceinline__ float sigf(float x) { return 1.0f / (1.0f + expf(-x)); }

// ---------------------------------------------------------------------------
// Column permutation: permuted col n -> gate = (n>>3)&3,
//   hcol = ((n>>6)<<4) | (((n>>5)&1)<<3) | (n&7)
// ---------------------------------------------------------------------------
__global__ void transform_x(const float* __restrict__ x) {
    uint32_t p = blockIdx.x * blockDim.x + threadIdx.x;   // 8,388,608 total
    int j    = p & 3;
    int lane = (p >> 2) & 31;
    int kb   = (p >> 7) & 1;
    int mb   = (p >> 8) & 7;
    int kt   = (p >> 11) & 7;
    int mt   = (p >> 14) & 1;
    int t    = p >> 15;
    int rowp = (lane >> 2) + 8 * (j & 1);
    int kp   = (lane & 3) * 2 + 8 * (j >> 1);
    int b    = mt * 128 + mb * 16 + rowp;
    int i    = kt * 32 + kb * 16 + kp;
    const float* src = x + ((long)b * TT + t) * II + i;
    __half2 v = __floats2half2_rn(src[0], src[1]);
    g_xp[p] = *(uint32_t*)&v;
}

__global__ void transform_W(const float* __restrict__ Wx, const float* __restrict__ Wh) {
    uint32_t p = blockIdx.x * blockDim.x + threadIdx.x;
    if (p >= (uint32_t)64 * NKT * B_IMG) return;
    int j    = p & 3;
    int lane = (p >> 2) & 31;
    int kb   = (p >> 7) & 1;
    int nbp  = (p >> 8) & 3;
    int kt   = (int)((p >> 10) % NKT);
    int ctan = (int)((p >> 10) / NKT);
    int nb   = nbp * 2 + (j >> 1);
    int r    = j & 1;
    int n    = ctan * 64 + nb * 8 + (lane >> 2);
    int gate = (n >> 3) & 3;
    int hcol = ((n >> 6) << 4) | (((n >> 5) & 1) << 3) | (n & 7);
    int col  = gate * HH + hcol;
    int kg   = kt * 32 + kb * 16 + r * 8 + (lane & 3) * 2;
    float v0 = (kg < II)     ? Wx[(long)kg * NG + col]       : Wh[(long)(kg - II) * NG + col];
    float v1 = (kg + 1 < II) ? Wx[(long)(kg + 1) * NG + col] : Wh[(long)(kg + 1 - II) * NG + col];
    __half2 v = __floats2half2_rn(v0, v1);
    g_Wp[p] = *(uint32_t*)&v;
}

__global__ void init_state(const float* __restrict__ h0, const float* __restrict__ c0) {
    uint32_t p = blockIdx.x * blockDim.x + threadIdx.x;
    if (p >= 262144) return;
    if (p < 131072) {   // h0 -> packed A images
        int j    = p & 3;
        int lane = (p >> 2) & 31;
        int kb   = (p >> 7) & 1;
        int mb   = (p >> 8) & 7;
        int hkt  = (p >> 11) & 31;
        int mt   = (p >> 16) & 1;
        int rowp = (lane >> 2) + 8 * (j & 1);
        int kp   = (lane & 3) * 2 + 8 * (j >> 1);
        int b    = mt * 128 + mb * 16 + rowp;
        int hc   = hkt * 32 + kb * 16 + kp;
        __half2 v = __floats2half2_rn(h0[b * HH + hc], h0[b * HH + hc + 1]);
        g_hp[0][p] = *(uint32_t*)&v;
    }
    g_c[p] = c0[p];
}

// ---------------------------------------------------------------------------
__device__ __forceinline__ void cp16(uint32_t saddr, const void* g) {
    asm volatile("cp.async.cg.shared.global [%0], [%1], 16;\n" :: "r"(saddr), "l"(g));
}
#define CP_COMMIT() asm volatile("cp.async.commit_group;\n" ::: "memory")
#define CP_WAIT(N)  asm volatile("cp.async.wait_group %0;\n" :: "n"(N) : "memory")

__device__ __forceinline__ void mma16816(float* d, const uint4& a, uint32_t b0, uint32_t b1) {
    asm volatile(
        "mma.sync.aligned.m16n8k16.row.col.f32.f16.f16.f32 "
        "{%0,%1,%2,%3}, {%4,%5,%6,%7}, {%8,%9}, {%0,%1,%2,%3};"
        : "+f"(d[0]), "+f"(d[1]), "+f"(d[2]), "+f"(d[3])
        : "r"(a.x), "r"(a.y), "r"(a.z), "r"(a.w), "r"(b0), "r"(b1));
}

// ---------------------------------------------------------------------------
// Per-step fused kernel: BM=64 half-tiles, 2 CTAs/SM for barrier overlap.
// ---------------------------------------------------------------------------
__global__ void __launch_bounds__(256, 2)
lstm_step(const float* __restrict__ bias,   // (4H,)
          float* __restrict__ out,          // outputs | hN | cN
          int t, int srcbuf)
{
    extern __shared__ uint4 smem[];
    uint4* sA4 = smem;                      // [4][512] uint4 (8KB/stage)
    uint4* sB4 = smem + STAGES * 512;       // [4][512] uint4 (8KB/stage)

    const uint32_t* __restrict__ hsrc = g_hp[srcbuf];
    uint32_t*       __restrict__ hdst = g_hp[srcbuf ^ 1];

    const int tid    = threadIdx.x;
    const int lane   = tid & 31;
    const int warp   = tid >> 5;
    const int warp_m = warp >> 1;        // 0..3 (16 rows each)
    const int warp_n = warp & 1;         // 0..1 (32 cols each)
    const int ctan   = blockIdx.x;       // 0..63
    const int mt4    = blockIdx.y;       // 0..3 (64-row tile)
    const int mt     = mt4 >> 1;         // 128-row image index
    const int half64 = mt4 & 1;          // which half of the image

    const uint32_t sA_b = (uint32_t)__cvta_generic_to_shared(sA4);
    const uint32_t sB_b = (uint32_t)__cvta_generic_to_shared(sB4);

    // columns this thread owns: hbase, hbase+1 (for all 4 gates)
    const int hbase = ctan * 16 + warp_n * 8 + 2 * (lane & 3);

    float acc[4][4];
    #pragma unroll
    for (int g = 0; g < 4; g++) {
        float b0 = __ldg(bias + g * HH + hbase);
        float b1 = __ldg(bias + g * HH + hbase + 1);
        acc[g][0] = b0; acc[g][1] = b1; acc[g][2] = b0; acc[g][3] = b1;
    }

    // stage loader: two 32-k half-images for A (contiguous 1024-uint32 slices),
    // two full 32-k B images. 4 cp16 per thread.
    auto issue = [&](int st) {
        int s = st & (STAGES - 1);
        #pragma unroll
        for (int img = 0; img < 2; img++) {
            int kt = st * 2 + img;
            const uint32_t* asrc = (st < XST)
                ? g_xp + ((long)(t * 2 + mt) * XKT + kt) * A_IMG + half64 * 1024
                : hsrc + (long)(mt * 32 + (kt - XKT)) * A_IMG + half64 * 1024;
            const uint32_t* bsrc = g_Wp + ((long)ctan * NKT + kt) * B_IMG;
            cp16(sA_b + (uint32_t)(s * 512 + img * 256 + tid) * 16, asrc + tid * 4);
            cp16(sB_b + (uint32_t)(s * 512 + img * 256 + tid) * 16, bsrc + tid * 4);
        }
    };

    issue(0); CP_COMMIT();
    issue(1); CP_COMMIT();
    issue(2); CP_COMMIT();

    for (int st = 0; st < NST; st++) {
        CP_WAIT(2);
        __syncthreads();

        int s = st & (STAGES - 1);
        const uint4* A  = sA4 + s * 512;
        const uint4* Bm = sB4 + s * 512;

        // preload all stage fragments, then 16 MMAs
        uint4 af[4];
        uint4 bf[8];
        #pragma unroll
        for (int kk = 0; kk < 4; kk++)   // kk = img*2 + kb
            af[kk] = A[(kk >> 1) * 256 + (warp_m * 2 + (kk & 1)) * 32 + lane];
        #pragma unroll
        for (int kk = 0; kk < 4; kk++) {
            #pragma unroll
            for (int np = 0; np < 2; np++)
                bf[kk * 2 + np] =
                    Bm[(kk >> 1) * 256 + ((warp_n * 2 + np) * 2 + (kk & 1)) * 32 + lane];
        }
        #pragma unroll
        for (int kk = 0; kk < 4; kk++) {
            mma16816(acc[0], af[kk], bf[kk * 2].x,     bf[kk * 2].y);
            mma16816(acc[1], af[kk], bf[kk * 2].z,     bf[kk * 2].w);
            mma16816(acc[2], af[kk], bf[kk * 2 + 1].x, bf[kk * 2 + 1].y);
            mma16816(acc[3], af[kk], bf[kk * 2 + 1].z, bf[kk * 2 + 1].w);
        }

        if (st + 3 < NST) issue(st + 3);   // stage (st-1)&3: readers passed barrier above
        CP_COMMIT();
    }

    // ---- epilogue ----------------------------------------------------------
    #pragma unroll
    for (int half = 0; half < 2; half++) {
        int m_loc = warp_m * 16 + (lane >> 2) + half * 8;   // 0..63 within CTA
        int r = mt4 * 64 + m_loc;                           // global row
        long cidx = (long)r * HH + hbase;
        float2 cold = *(const float2*)(g_c + cidx);
        float hn[2], cn[2];
        #pragma unroll
        for (int j = 0; j < 2; j++) {
            int c2 = half * 2 + j;
            float ii = sigf(acc[0][c2]);
            float ff = sigf(acc[1][c2]);
            float tg = tanhf(acc[2][c2]);
            float oo = sigf(acc[3][c2]);
            float cnew = ff * (j ? cold.y : cold.x) + ii * tg;
            cn[j] = cnew;
            hn[j] = oo * tanhf(cnew);
        }
        *(float2*)(g_c + cidx) = make_float2(cn[0], cn[1]);
        *(float2*)(out + ((long)r * TT + t) * HH + hbase) = make_float2(hn[0], hn[1]);
        if (t == TT - 1) {
            *(float2*)(out + BTH + (long)r * HH + hbase)      = make_float2(hn[0], hn[1]);
            *(float2*)(out + BTH + BH + (long)r * HH + hbase) = make_float2(cn[0], cn[1]);
        }
        float h0s = hn[0], h1s = hn[1];
        if (hbase == 0) {
            h0s = hn[0] + TAUc * (MHUc * hn[0] + hn[1] / MHUc);
            h1s = hn[1] - TAUc * (MHUc * hn[0]);
        }
        // carry store into next step's packed A image
        int mb   = (r >> 4) & 7;        // 16-row block within the 128-row image
        int rowp = r & 15;
        int hkt  = hbase >> 5;
        int kb   = (hbase >> 4) & 1;
        int jj   = ((rowp >> 3) & 1) | ((((hbase & 15) >= 8) ? 1 : 0) << 1);
        int lanep = ((rowp & 7) << 2) | ((hbase & 7) >> 1);
        __half2 hv = __floats2half2_rn(h0s, h1s);
        hdst[(long)(mt * 32 + hkt) * A_IMG + ((mb * 2 + kb) * 32 + lanep) * 4 + jj] =
            *(uint32_t*)&hv;
    }
}

// ---------------------------------------------------------------------------
extern "C" void kernel_launch(void* const* d_in, const int* in_sizes, int n_in,
                              void* d_out, int out_size) {
    const float* x  = (const float*)d_in[0];
    const float* h0 = (const float*)d_in[1];
    const float* c0 = (const float*)d_in[2];
    const float* Wx = (const float*)d_in[3];
    const float* Wh = (const float*)d_in[4];
    const float* b  = (const float*)d_in[5];
    float* out = (float*)d_out;

    cudaFuncSetAttribute(lstm_step, cudaFuncAttributeMaxDynamicSharedMemorySize, DSMEM);

    transform_x<<<32768, 256>>>(x);
    {
        long total = (long)64 * NKT * B_IMG;
        transform_W<<<(int)((total + 255) / 256), 256>>>(Wx, Wh);
    }
    init_state<<<1024, 256>>>(h0, c0);

    for (int t = 0; t < TT; t++) {
        lstm_step<<<dim3(64, 4), 256, DSMEM>>>(b, out, t, t & 1);
    }
}

// round 8
// speedup vs baseline: 1.0463x; 1.0463x over previous
#include <cuda_runtime.h>
#include <cuda_fp16.h>
#include <math.h>
#include <stdint.h>

// Problem constants
#define BB   256
#define TT   256
#define II   256
#define HH   1024
#define KTOT 1280
#define NG   4096
#define TAUc 0.05f
#define MHUc 1.5f
#define BTH  ((long)BB * TT * HH)
#define BH   ((long)BB * HH)

// Tiling: BM=128, BN=64, stage BK=64 (4 x k16). Grid (64 ctan, 2 mtile) = 128 CTAs.
// 256 threads = 8 warps, 4 m-warps x 2 n-warps, warp tile 32x32.
#define NKT    40          // 32-k images (KTOT/32)
#define XKT    8           // x images per (t, mt)
#define NST    20          // stages per step (KTOT/64)
#define XST    4           // x stages
#define STAGES 5
#define A_IMG  2048        // uint32 per 32-k A image (128 rows x 32 k fp16)
#define B_IMG  1024        // uint32 per 32-k B image (64 n x 32 k fp16)
// per-CTA stage: A 16KB + B 8KB = 24KB
#define DSMEM  (STAGES * 1536 * 16)   // 120KB dynamic smem

// ---------------------------------------------------------------------------
// Persistent scratch: operand images stored exactly as smem stages should look
// (mma-fragment register images, fp16) -> per-step copies are pure linear.
// A image: [mb(8)][kb16(2)][lane(32)][reg(4)] uint32 (128 rows x 32 k):
//   reg j, half h: row' = (lane>>2) + 8*(j&1), k' = (lane&3)*2 + 8*(j>>1) + h
// B image: [nbp(4)][kb16(2)][lane(32)][j(4)] uint32:
//   nb = nbp*2 + (j>>1), r = j&1: k = r*8 + (lane&3)*2 + h, n = nb*8 + (lane>>2)
// ---------------------------------------------------------------------------
__device__ uint32_t g_xp[(long)TT * 2 * XKT * A_IMG];
__device__ uint32_t g_hp[2][2 * 32 * A_IMG];
__device__ uint32_t g_Wp[(long)64 * NKT * B_IMG];
__device__ float    g_c[BB * HH];

__device__ __forceinline__ float sigf(float x) { return 1.0f / (1.0f + expf(-x)); }

// ---------------------------------------------------------------------------
// Column permutation: permuted col n -> gate = (n>>3)&3,
//   hcol = ((n>>6)<<4) | (((n>>5)&1)<<3) | (n&7)
// ---------------------------------------------------------------------------
__global__ void transform_x(const float* __restrict__ x) {
    uint32_t p = blockIdx.x * blockDim.x + threadIdx.x;   // 8,388,608 total
    int j    = p & 3;
    int lane = (p >> 2) & 31;
    int kb   = (p >> 7) & 1;
    int mb   = (p >> 8) & 7;
    int kt   = (p >> 11) & 7;
    int mt   = (p >> 14) & 1;
    int t    = p >> 15;
    int rowp = (lane >> 2) + 8 * (j & 1);
    int kp   = (lane & 3) * 2 + 8 * (j >> 1);
    int b    = mt * 128 + mb * 16 + rowp;
    int i    = kt * 32 + kb * 16 + kp;
    const float* src = x + ((long)b * TT + t) * II + i;
    __half2 v = __floats2half2_rn(src[0], src[1]);
    g_xp[p] = *(uint32_t*)&v;
}

__global__ void transform_W(const float* __restrict__ Wx, const float* __restrict__ Wh) {
    uint32_t p = blockIdx.x * blockDim.x + threadIdx.x;
    if (p >= (uint32_t)64 * NKT * B_IMG) return;
    int j    = p & 3;
    int lane = (p >> 2) & 31;
    int kb   = (p >> 7) & 1;
    int nbp  = (p >> 8) & 3;
    int kt   = (int)((p >> 10) % NKT);
    int ctan = (int)((p >> 10) / NKT);
    int nb   = nbp * 2 + (j >> 1);
    int r    = j & 1;
    int n    = ctan * 64 + nb * 8 + (lane >> 2);
    int gate = (n >> 3) & 3;
    int hcol = ((n >> 6) << 4) | (((n >> 5) & 1) << 3) | (n & 7);
    int col  = gate * HH + hcol;
    int kg   = kt * 32 + kb * 16 + r * 8 + (lane & 3) * 2;
    float v0 = (kg < II)     ? Wx[(long)kg * NG + col]       : Wh[(long)(kg - II) * NG + col];
    float v1 = (kg + 1 < II) ? Wx[(long)(kg + 1) * NG + col] : Wh[(long)(kg + 1 - II) * NG + col];
    __half2 v = __floats2half2_rn(v0, v1);
    g_Wp[p] = *(uint32_t*)&v;
}

__global__ void init_state(const float* __restrict__ h0, const float* __restrict__ c0) {
    uint32_t p = blockIdx.x * blockDim.x + threadIdx.x;
    if (p >= 262144) return;
    if (p < 131072) {   // h0 -> packed A images
        int j    = p & 3;
        int lane = (p >> 2) & 31;
        int kb   = (p >> 7) & 1;
        int mb   = (p >> 8) & 7;
        int hkt  = (p >> 11) & 31;
        int mt   = (p >> 16) & 1;
        int rowp = (lane >> 2) + 8 * (j & 1);
        int kp   = (lane & 3) * 2 + 8 * (j >> 1);
        int b    = mt * 128 + mb * 16 + rowp;
        int hc   = hkt * 32 + kb * 16 + kp;
        __half2 v = __floats2half2_rn(h0[b * HH + hc], h0[b * HH + hc + 1]);
        g_hp[0][p] = *(uint32_t*)&v;
    }
    g_c[p] = c0[p];
}

// ---------------------------------------------------------------------------
__device__ __forceinline__ void cp16(uint32_t saddr, const void* g) {
    asm volatile("cp.async.cg.shared.global [%0], [%1], 16;\n" :: "r"(saddr), "l"(g));
}
#define CP_COMMIT() asm volatile("cp.async.commit_group;\n" ::: "memory")
#define CP_WAIT(N)  asm volatile("cp.async.wait_group %0;\n" :: "n"(N) : "memory")

__device__ __forceinline__ void mma16816(float* d, const uint4& a, uint32_t b0, uint32_t b1) {
    asm volatile(
        "mma.sync.aligned.m16n8k16.row.col.f32.f16.f16.f32 "
        "{%0,%1,%2,%3}, {%4,%5,%6,%7}, {%8,%9}, {%0,%1,%2,%3};"
        : "+f"(d[0]), "+f"(d[1]), "+f"(d[2]), "+f"(d[3])
        : "r"(a.x), "r"(a.y), "r"(a.z), "r"(a.w), "r"(b0), "r"(b1));
}

// ---------------------------------------------------------------------------
// Per-step fused kernel: warp tile 32x32 (halved fragment traffic per MAC),
// 8 warps, 5-stage cp.async pipeline.
// ---------------------------------------------------------------------------
__global__ void __launch_bounds__(256, 1)
lstm_step(const float* __restrict__ bias,   // (4H,)
          float* __restrict__ out,          // outputs | hN | cN
          int t, int srcbuf)
{
    extern __shared__ uint4 smem[];
    uint4* sA4 = smem;                      // [5][1024] uint4 (16KB/stage)
    uint4* sB4 = smem + STAGES * 1024;      // [5][512]  uint4 (8KB/stage)

    const uint32_t* __restrict__ hsrc = g_hp[srcbuf];
    uint32_t*       __restrict__ hdst = g_hp[srcbuf ^ 1];

    const int tid    = threadIdx.x;
    const int lane   = tid & 31;
    const int warp   = tid >> 5;
    const int warp_m = warp >> 1;        // 0..3 (32 rows each)
    const int warp_n = warp & 1;         // 0..1 (32 cols each)
    const int ctan   = blockIdx.x;       // 0..63
    const int mt     = blockIdx.y;       // 0..1

    const uint32_t sA_b = (uint32_t)__cvta_generic_to_shared(sA4);
    const uint32_t sB_b = (uint32_t)__cvta_generic_to_shared(sB4);

    // columns this thread owns: hbase, hbase+1 (for all 4 gates)
    const int hbase = ctan * 16 + warp_n * 8 + 2 * (lane & 3);

    // acc[mb][gate][c]: mb = 16-row block within the warp's 32 rows
    float acc[2][4][4];
    #pragma unroll
    for (int g = 0; g < 4; g++) {
        float b0 = __ldg(bias + g * HH + hbase);
        float b1 = __ldg(bias + g * HH + hbase + 1);
        #pragma unroll
        for (int mb = 0; mb < 2; mb++) {
            acc[mb][g][0] = b0; acc[mb][g][1] = b1;
            acc[mb][g][2] = b0; acc[mb][g][3] = b1;
        }
    }

    // stage loader: A 1024 uint4 (4/thread), B 512 uint4 (2/thread)
    auto issue = [&](int st) {
        int s = st % STAGES;
        const uint32_t* asrc = (st < XST)
            ? g_xp + ((long)(t * 2 + mt) * XKT + st * 2) * A_IMG
            : hsrc + (long)(mt * 32 + (st - XST) * 2) * A_IMG;
        const uint32_t* bsrc = g_Wp + ((long)ctan * NKT + st * 2) * B_IMG;
        #pragma unroll
        for (int r = 0; r < 4; r++) {
            int idx = tid + 256 * r;
            cp16(sA_b + (uint32_t)(s * 1024 + idx) * 16, asrc + idx * 4);
        }
        #pragma unroll
        for (int r = 0; r < 2; r++) {
            int idx = tid + 256 * r;
            cp16(sB_b + (uint32_t)(s * 512 + idx) * 16, bsrc + idx * 4);
        }
    };

    issue(0); CP_COMMIT();
    issue(1); CP_COMMIT();
    issue(2); CP_COMMIT();
    issue(3); CP_COMMIT();

    for (int st = 0; st < NST; st++) {
        CP_WAIT(3);
        __syncthreads();

        int s = st % STAGES;
        const uint4* A  = sA4 + s * 1024;
        const uint4* Bm = sB4 + s * 512;

        #pragma unroll
        for (int kk = 0; kk < 4; kk++) {     // kk = img*2 + kb (k16 chunks)
            uint4 af0 = A[(kk >> 1) * 512 + ((warp_m * 2 + 0) * 2 + (kk & 1)) * 32 + lane];
            uint4 af1 = A[(kk >> 1) * 512 + ((warp_m * 2 + 1) * 2 + (kk & 1)) * 32 + lane];
            uint4 bf0 = Bm[(kk >> 1) * 256 + ((warp_n * 2 + 0) * 2 + (kk & 1)) * 32 + lane];
            uint4 bf1 = Bm[(kk >> 1) * 256 + ((warp_n * 2 + 1) * 2 + (kk & 1)) * 32 + lane];
            mma16816(acc[0][0], af0, bf0.x, bf0.y);
            mma16816(acc[0][1], af0, bf0.z, bf0.w);
            mma16816(acc[0][2], af0, bf1.x, bf1.y);
            mma16816(acc[0][3], af0, bf1.z, bf1.w);
            mma16816(acc[1][0], af1, bf0.x, bf0.y);
            mma16816(acc[1][1], af1, bf0.z, bf0.w);
            mma16816(acc[1][2], af1, bf1.x, bf1.y);
            mma16816(acc[1][3], af1, bf1.z, bf1.w);
        }

        if (st + 4 < NST) issue(st + 4);   // stage (st-1)%5: readers passed barrier above
        CP_COMMIT();
    }

    // ---- epilogue ----------------------------------------------------------
    #pragma unroll
    for (int mb = 0; mb < 2; mb++) {
        #pragma unroll
        for (int half = 0; half < 2; half++) {
            int m_loc = warp_m * 32 + mb * 16 + (lane >> 2) + half * 8;
            int r = mt * 128 + m_loc;
            long cidx = (long)r * HH + hbase;
            float2 cold = *(const float2*)(g_c + cidx);
            float hn[2], cn[2];
            #pragma unroll
            for (int j = 0; j < 2; j++) {
                int c2 = half * 2 + j;
                float ii = sigf(acc[mb][0][c2]);
                float ff = sigf(acc[mb][1][c2]);
                float tg = tanhf(acc[mb][2][c2]);
                float oo = sigf(acc[mb][3][c2]);
                float cnew = ff * (j ? cold.y : cold.x) + ii * tg;
                cn[j] = cnew;
                hn[j] = oo * tanhf(cnew);
            }
            *(float2*)(g_c + cidx) = make_float2(cn[0], cn[1]);
            *(float2*)(out + ((long)r * TT + t) * HH + hbase) = make_float2(hn[0], hn[1]);
            if (t == TT - 1) {
                *(float2*)(out + BTH + (long)r * HH + hbase)      = make_float2(hn[0], hn[1]);
                *(float2*)(out + BTH + BH + (long)r * HH + hbase) = make_float2(cn[0], cn[1]);
            }
            float h0s = hn[0], h1s = hn[1];
            if (hbase == 0) {
                h0s = hn[0] + TAUc * (MHUc * hn[0] + hn[1] / MHUc);
                h1s = hn[1] - TAUc * (MHUc * hn[0]);
            }
            // carry store into next step's packed A image
            int mbb  = m_loc >> 4;
            int rowp = m_loc & 15;
            int hkt  = hbase >> 5;
            int kb   = (hbase >> 4) & 1;
            int jj   = ((rowp >> 3) & 1) | ((((hbase & 15) >= 8) ? 1 : 0) << 1);
            int lanep = ((rowp & 7) << 2) | ((hbase & 7) >> 1);
            __half2 hv = __floats2half2_rn(h0s, h1s);
            hdst[(long)(mt * 32 + hkt) * A_IMG + ((mbb * 2 + kb) * 32 + lanep) * 4 + jj] =
                *(uint32_t*)&hv;
        }
    }
}

// ---------------------------------------------------------------------------
extern "C" void kernel_launch(void* const* d_in, const int* in_sizes, int n_in,
                              void* d_out, int out_size) {
    const float* x  = (const float*)d_in[0];
    const float* h0 = (const float*)d_in[1];
    const float* c0 = (const float*)d_in[2];
    const float* Wx = (const float*)d_in[3];
    const float* Wh = (const float*)d_in[4];
    const float* b  = (const float*)d_in[5];
    float* out = (float*)d_out;

    cudaFuncSetAttribute(lstm_step, cudaFuncAttributeMaxDynamicSharedMemorySize, DSMEM);

    transform_x<<<32768, 256>>>(x);
    {
        long total = (long)64 * NKT * B_IMG;
        transform_W<<<(int)((total + 255) / 256), 256>>>(Wx, Wh);
    }
    init_state<<<1024, 256>>>(h0, c0);

    for (int t = 0; t < TT; t++) {
        lstm_step<<<dim3(64, 2), 256, DSMEM>>>(b, out, t, t & 1);
    }
}

// round 9
// speedup vs baseline: 1.1837x; 1.1313x over previous
#include <cuda_runtime.h>
#include <cuda_fp16.h>
#include <math.h>
#include <stdint.h>

// Problem constants
#define BB   256
#define TT   256
#define II   256
#define HH   1024
#define KTOT 1280
#define NG   4096
#define TAUc 0.05f
#define MHUc 1.5f
#define BTH  ((long)BB * TT * HH)
#define BH   ((long)BB * HH)

// Tiling: BM=128, BN=64, stage BK=64 (4 x k16). Grid (64 ctan, 2 mtile) = 128 CTAs,
// persistent (1/SM). 256 threads = 8 warps, 4m x 2n, warp tile 32x32.
#define NKT    40          // 32-k images (KTOT/32)
#define XKT    8           // x images per (t, mt)
#define NST    20          // stages per step (KTOT/64)
#define XST    4           // x stages
#define STAGES 5
#define A_IMG  2048        // uint32 per 32-k A image (128 rows x 32 k fp16)
#define B_IMG  1024        // uint32 per 32-k B image (64 n x 32 k fp16)
#define DSMEM  (STAGES * 1536 * 16)   // 120KB dynamic smem
#define NCTA   128

// ---------------------------------------------------------------------------
// Persistent scratch: operand images stored exactly as smem stages should look
// (mma-fragment register images, fp16) -> per-step copies are pure linear.
// A image: [mb(8)][kb16(2)][lane(32)][reg(4)] uint32 (128 rows x 32 k):
//   reg j, half h: row' = (lane>>2) + 8*(j&1), k' = (lane&3)*2 + 8*(j>>1) + h
// B image: [nbp(4)][kb16(2)][lane(32)][j(4)] uint32:
//   nb = nbp*2 + (j>>1), r = j&1: k = r*8 + (lane&3)*2 + h, n = nb*8 + (lane>>2)
// ---------------------------------------------------------------------------
__device__ uint32_t g_xp[(long)TT * 2 * XKT * A_IMG];
__device__ uint32_t g_hp[2][2 * 32 * A_IMG];
__device__ uint32_t g_Wp[(long)64 * NKT * B_IMG];
__device__ float    g_c[BB * HH];
__device__ unsigned g_bar;                 // global phase barrier (monotonic)

__device__ __forceinline__ float tanh_fast(float x) {
    float r;
    asm("tanh.approx.f32 %0, %1;" : "=f"(r) : "f"(x));
    return r;
}
__device__ __forceinline__ float sig_fast(float x) {
    return 0.5f * tanh_fast(0.5f * x) + 0.5f;
}

// ---------------------------------------------------------------------------
// Column permutation: permuted col n -> gate = (n>>3)&3,
//   hcol = ((n>>6)<<4) | (((n>>5)&1)<<3) | (n&7)
// ---------------------------------------------------------------------------
__global__ void transform_x(const float* __restrict__ x) {
    uint32_t p = blockIdx.x * blockDim.x + threadIdx.x;   // 8,388,608 total
    int j    = p & 3;
    int lane = (p >> 2) & 31;
    int kb   = (p >> 7) & 1;
    int mb   = (p >> 8) & 7;
    int kt   = (p >> 11) & 7;
    int mt   = (p >> 14) & 1;
    int t    = p >> 15;
    int rowp = (lane >> 2) + 8 * (j & 1);
    int kp   = (lane & 3) * 2 + 8 * (j >> 1);
    int b    = mt * 128 + mb * 16 + rowp;
    int i    = kt * 32 + kb * 16 + kp;
    const float* src = x + ((long)b * TT + t) * II + i;
    __half2 v = __floats2half2_rn(src[0], src[1]);
    g_xp[p] = *(uint32_t*)&v;
}

__global__ void transform_W(const float* __restrict__ Wx, const float* __restrict__ Wh) {
    uint32_t p = blockIdx.x * blockDim.x + threadIdx.x;
    if (p >= (uint32_t)64 * NKT * B_IMG) return;
    int j    = p & 3;
    int lane = (p >> 2) & 31;
    int kb   = (p >> 7) & 1;
    int nbp  = (p >> 8) & 3;
    int kt   = (int)((p >> 10) % NKT);
    int ctan = (int)((p >> 10) / NKT);
    int nb   = nbp * 2 + (j >> 1);
    int r    = j & 1;
    int n    = ctan * 64 + nb * 8 + (lane >> 2);
    int gate = (n >> 3) & 3;
    int hcol = ((n >> 6) << 4) | (((n >> 5) & 1) << 3) | (n & 7);
    int col  = gate * HH + hcol;
    int kg   = kt * 32 + kb * 16 + r * 8 + (lane & 3) * 2;
    float v0 = (kg < II)     ? Wx[(long)kg * NG + col]       : Wh[(long)(kg - II) * NG + col];
    float v1 = (kg + 1 < II) ? Wx[(long)(kg + 1) * NG + col] : Wh[(long)(kg + 1 - II) * NG + col];
    __half2 v = __floats2half2_rn(v0, v1);
    g_Wp[p] = *(uint32_t*)&v;
}

__global__ void init_state(const float* __restrict__ h0, const float* __restrict__ c0) {
    uint32_t p = blockIdx.x * blockDim.x + threadIdx.x;
    if (p == 0) g_bar = 0u;
    if (p >= 262144) return;
    if (p < 131072) {   // h0 -> packed A images
        int j    = p & 3;
        int lane = (p >> 2) & 31;
        int kb   = (p >> 7) & 1;
        int mb   = (p >> 8) & 7;
        int hkt  = (p >> 11) & 31;
        int mt   = (p >> 16) & 1;
        int rowp = (lane >> 2) + 8 * (j & 1);
        int kp   = (lane & 3) * 2 + 8 * (j >> 1);
        int b    = mt * 128 + mb * 16 + rowp;
        int hc   = hkt * 32 + kb * 16 + kp;
        __half2 v = __floats2half2_rn(h0[b * HH + hc], h0[b * HH + hc + 1]);
        g_hp[0][p] = *(uint32_t*)&v;
    }
    g_c[p] = c0[p];
}

// ---------------------------------------------------------------------------
__device__ __forceinline__ void cp16(uint32_t saddr, const void* g) {
    asm volatile("cp.async.cg.shared.global [%0], [%1], 16;\n" :: "r"(saddr), "l"(g));
}
#define CP_COMMIT() asm volatile("cp.async.commit_group;\n" ::: "memory")
#define CP_WAIT(N)  asm volatile("cp.async.wait_group %0;\n" :: "n"(N) : "memory")

__device__ __forceinline__ void mma16816(float* d, const uint4& a, uint32_t b0, uint32_t b1) {
    asm volatile(
        "mma.sync.aligned.m16n8k16.row.col.f32.f16.f16.f32 "
        "{%0,%1,%2,%3}, {%4,%5,%6,%7}, {%8,%9}, {%0,%1,%2,%3};"
        : "+f"(d[0]), "+f"(d[1]), "+f"(d[2]), "+f"(d[3])
        : "r"(a.x), "r"(a.y), "r"(a.z), "r"(a.w), "r"(b0), "r"(b1));
}

// ---------------------------------------------------------------------------
// Persistent kernel: all 256 timesteps, global barrier between steps.
// ---------------------------------------------------------------------------
__global__ void __launch_bounds__(256, 1)
lstm_persist(const float* __restrict__ bias,   // (4H,)
             float* __restrict__ out)          // outputs | hN | cN
{
    extern __shared__ uint4 smem[];
    uint4* sA4 = smem;                      // [5][1024] uint4
    uint4* sB4 = smem + STAGES * 1024;      // [5][512]  uint4

    const int tid    = threadIdx.x;
    const int lane   = tid & 31;
    const int warp   = tid >> 5;
    const int warp_m = warp >> 1;        // 0..3 (32 rows)
    const int warp_n = warp & 1;         // 0..1 (32 cols)
    const int ctan   = blockIdx.x;       // 0..63
    const int mt     = blockIdx.y;       // 0..1

    const uint32_t sA_b = (uint32_t)__cvta_generic_to_shared(sA4);
    const uint32_t sB_b = (uint32_t)__cvta_generic_to_shared(sB4);

    const int hbase = ctan * 16 + warp_n * 8 + 2 * (lane & 3);

    // bias registers hoisted across all timesteps
    float bg0[4], bg1[4];
    #pragma unroll
    for (int g = 0; g < 4; g++) {
        bg0[g] = __ldg(bias + g * HH + hbase);
        bg1[g] = __ldg(bias + g * HH + hbase + 1);
    }

    for (int t = 0; t < TT; t++) {
        const int srcbuf = t & 1;
        const uint32_t* __restrict__ hsrc = g_hp[srcbuf];
        uint32_t*       __restrict__ hdst = g_hp[srcbuf ^ 1];

        float acc[2][4][4];
        #pragma unroll
        for (int g = 0; g < 4; g++) {
            #pragma unroll
            for (int mb = 0; mb < 2; mb++) {
                acc[mb][g][0] = bg0[g]; acc[mb][g][1] = bg1[g];
                acc[mb][g][2] = bg0[g]; acc[mb][g][3] = bg1[g];
            }
        }

        auto issue = [&](int st) {
            int s = st % STAGES;
            const uint32_t* asrc = (st < XST)
                ? g_xp + ((long)(t * 2 + mt) * XKT + st * 2) * A_IMG
                : hsrc + (long)(mt * 32 + (st - XST) * 2) * A_IMG;
            const uint32_t* bsrc = g_Wp + ((long)ctan * NKT + st * 2) * B_IMG;
            #pragma unroll
            for (int r = 0; r < 4; r++) {
                int idx = tid + 256 * r;
                cp16(sA_b + (uint32_t)(s * 1024 + idx) * 16, asrc + idx * 4);
            }
            #pragma unroll
            for (int r = 0; r < 2; r++) {
                int idx = tid + 256 * r;
                cp16(sB_b + (uint32_t)(s * 512 + idx) * 16, bsrc + idx * 4);
            }
        };

        issue(0); CP_COMMIT();
        issue(1); CP_COMMIT();
        issue(2); CP_COMMIT();
        issue(3); CP_COMMIT();

        for (int st = 0; st < NST; st++) {
            CP_WAIT(3);
            __syncthreads();

            int s = st % STAGES;
            const uint4* A  = sA4 + s * 1024;
            const uint4* Bm = sB4 + s * 512;

            #pragma unroll
            for (int kk = 0; kk < 4; kk++) {
                uint4 af0 = A[(kk >> 1) * 512 + ((warp_m * 2 + 0) * 2 + (kk & 1)) * 32 + lane];
                uint4 af1 = A[(kk >> 1) * 512 + ((warp_m * 2 + 1) * 2 + (kk & 1)) * 32 + lane];
                uint4 bf0 = Bm[(kk >> 1) * 256 + ((warp_n * 2 + 0) * 2 + (kk & 1)) * 32 + lane];
                uint4 bf1 = Bm[(kk >> 1) * 256 + ((warp_n * 2 + 1) * 2 + (kk & 1)) * 32 + lane];
                mma16816(acc[0][0], af0, bf0.x, bf0.y);
                mma16816(acc[0][1], af0, bf0.z, bf0.w);
                mma16816(acc[0][2], af0, bf1.x, bf1.y);
                mma16816(acc[0][3], af0, bf1.z, bf1.w);
                mma16816(acc[1][0], af1, bf0.x, bf0.y);
                mma16816(acc[1][1], af1, bf0.z, bf0.w);
                mma16816(acc[1][2], af1, bf1.x, bf1.y);
                mma16816(acc[1][3], af1, bf1.z, bf1.w);
            }

            if (st + 4 < NST) issue(st + 4);
            CP_COMMIT();
        }

        // ---- epilogue -------------------------------------------------------
        #pragma unroll
        for (int mb = 0; mb < 2; mb++) {
            #pragma unroll
            for (int half = 0; half < 2; half++) {
                int m_loc = warp_m * 32 + mb * 16 + (lane >> 2) + half * 8;
                int r = mt * 128 + m_loc;
                long cidx = (long)r * HH + hbase;
                float2 cold = *(const float2*)(g_c + cidx);
                float hn[2], cn[2];
                #pragma unroll
                for (int j = 0; j < 2; j++) {
                    int c2 = half * 2 + j;
                    float ii = sig_fast(acc[mb][0][c2]);
                    float ff = sig_fast(acc[mb][1][c2]);
                    float tg = tanh_fast(acc[mb][2][c2]);
                    float oo = sig_fast(acc[mb][3][c2]);
                    float cnew = ff * (j ? cold.y : cold.x) + ii * tg;
                    cn[j] = cnew;
                    hn[j] = oo * tanh_fast(cnew);
                }
                *(float2*)(g_c + cidx) = make_float2(cn[0], cn[1]);
                *(float2*)(out + ((long)r * TT + t) * HH + hbase) = make_float2(hn[0], hn[1]);
                if (t == TT - 1) {
                    *(float2*)(out + BTH + (long)r * HH + hbase)      = make_float2(hn[0], hn[1]);
                    *(float2*)(out + BTH + BH + (long)r * HH + hbase) = make_float2(cn[0], cn[1]);
                }
                float h0s = hn[0], h1s = hn[1];
                if (hbase == 0) {
                    h0s = hn[0] + TAUc * (MHUc * hn[0] + hn[1] / MHUc);
                    h1s = hn[1] - TAUc * (MHUc * hn[0]);
                }
                int mbb  = m_loc >> 4;
                int rowp = m_loc & 15;
                int hkt  = hbase >> 5;
                int kb   = (hbase >> 4) & 1;
                int jj   = ((rowp >> 3) & 1) | ((((hbase & 15) >= 8) ? 1 : 0) << 1);
                int lanep = ((rowp & 7) << 2) | ((hbase & 7) >> 1);
                __half2 hv = __floats2half2_rn(h0s, h1s);
                hdst[(long)(mt * 32 + hkt) * A_IMG + ((mbb * 2 + kb) * 32 + lanep) * 4 + jj] =
                    *(uint32_t*)&hv;
            }
        }

        // ---- global phase barrier (skip after final step) --------------------
        if (t + 1 < TT) {
            __threadfence();                 // release h-carry writes to L2
            __syncthreads();                 // all warps' stores issued
            if (tid == 0) {
                atomicAdd(&g_bar, 1u);
                unsigned target = (unsigned)(NCTA * (t + 1));
                while (atomicAdd(&g_bar, 0u) < target) { }
            }
            __syncthreads();                 // fan-out: everyone past the barrier
        }
    }
}

// ---------------------------------------------------------------------------
extern "C" void kernel_launch(void* const* d_in, const int* in_sizes, int n_in,
                              void* d_out, int out_size) {
    const float* x  = (const float*)d_in[0];
    const float* h0 = (const float*)d_in[1];
    const float* c0 = (const float*)d_in[2];
    const float* Wx = (const float*)d_in[3];
    const float* Wh = (const float*)d_in[4];
    const float* b  = (const float*)d_in[5];
    float* out = (float*)d_out;

    cudaFuncSetAttribute(lstm_persist, cudaFuncAttributeMaxDynamicSharedMemorySize, DSMEM);

    transform_x<<<32768, 256>>>(x);
    {
        long total = (long)64 * NKT * B_IMG;
        transform_W<<<(int)((total + 255) / 256), 256>>>(Wx, Wh);
    }
    init_state<<<1024, 256>>>(h0, c0);

    lstm_persist<<<dim3(64, 2), 256, DSMEM>>>(b, out);
}

// round 10
// speedup vs baseline: 1.2260x; 1.0357x over previous
#include <cuda_runtime.h>
#include <cuda_fp16.h>
#include <math.h>
#include <stdint.h>

// Problem constants
#define BB   256
#define TT   256
#define II   256
#define HH   1024
#define KTOT 1280
#define NG   4096
#define TAUc 0.05f
#define MHUc 1.5f
#define BTH  ((long)BB * TT * HH)
#define BH   ((long)BB * HH)

// Tiling: BM=128, BN=64, stage BK=64 (4 x k16). Grid (64 ctan, 2 mtile) = 128 CTAs,
// persistent (1/SM). 256 threads = 8 warps, 4m x 2n, warp tile 32x32.
#define NKT    40          // 32-k images (KTOT/32)
#define XKT    8           // x images per (t, mt)
#define NST    20          // stages per step (KTOT/64)
#define XST    4           // x stages
#define STAGES 5
#define A_IMG  2048        // uint32 per 32-k A image (128 rows x 32 k fp16)
#define B_IMG  1024        // uint32 per 32-k B image (64 n x 32 k fp16)
#define DSMEM  (STAGES * 1536 * 16)   // 120KB dynamic smem

// ---------------------------------------------------------------------------
// Persistent scratch: operand images stored exactly as smem stages should look
// (mma-fragment register images, fp16) -> per-step copies are pure linear.
// A image: [mb(8)][kb16(2)][lane(32)][reg(4)] uint32 (128 rows x 32 k):
//   reg j, half h: row' = (lane>>2) + 8*(j&1), k' = (lane&3)*2 + 8*(j>>1) + h
// B image: [nbp(4)][kb16(2)][lane(32)][j(4)] uint32:
//   nb = nbp*2 + (j>>1), r = j&1: k = r*8 + (lane&3)*2 + h, n = nb*8 + (lane>>2)
// ---------------------------------------------------------------------------
__device__ uint32_t g_xp[(long)TT * 2 * XKT * A_IMG];
__device__ uint32_t g_hp[2][2 * 32 * A_IMG];
__device__ uint32_t g_Wp[(long)64 * NKT * B_IMG];
__device__ float    g_c[BB * HH];
__device__ unsigned g_bar[2];              // per-mtile phase barriers (monotonic)

__device__ __forceinline__ float tanh_fast(float x) {
    float r;
    asm("tanh.approx.f32 %0, %1;" : "=f"(r) : "f"(x));
    return r;
}
__device__ __forceinline__ float sig_fast(float x) {
    return 0.5f * tanh_fast(0.5f * x) + 0.5f;
}

// ---------------------------------------------------------------------------
// Column permutation: permuted col n -> gate = (n>>3)&3,
//   hcol = ((n>>6)<<4) | (((n>>5)&1)<<3) | (n&7)
// ---------------------------------------------------------------------------
__global__ void transform_x(const float* __restrict__ x) {
    uint32_t p = blockIdx.x * blockDim.x + threadIdx.x;   // 8,388,608 total
    int j    = p & 3;
    int lane = (p >> 2) & 31;
    int kb   = (p >> 7) & 1;
    int mb   = (p >> 8) & 7;
    int kt   = (p >> 11) & 7;
    int mt   = (p >> 14) & 1;
    int t    = p >> 15;
    int rowp = (lane >> 2) + 8 * (j & 1);
    int kp   = (lane & 3) * 2 + 8 * (j >> 1);
    int b    = mt * 128 + mb * 16 + rowp;
    int i    = kt * 32 + kb * 16 + kp;
    const float* src = x + ((long)b * TT + t) * II + i;
    __half2 v = __floats2half2_rn(src[0], src[1]);
    g_xp[p] = *(uint32_t*)&v;
}

__global__ void transform_W(const float* __restrict__ Wx, const float* __restrict__ Wh) {
    uint32_t p = blockIdx.x * blockDim.x + threadIdx.x;
    if (p >= (uint32_t)64 * NKT * B_IMG) return;
    int j    = p & 3;
    int lane = (p >> 2) & 31;
    int kb   = (p >> 7) & 1;
    int nbp  = (p >> 8) & 3;
    int kt   = (int)((p >> 10) % NKT);
    int ctan = (int)((p >> 10) / NKT);
    int nb   = nbp * 2 + (j >> 1);
    int r    = j & 1;
    int n    = ctan * 64 + nb * 8 + (lane >> 2);
    int gate = (n >> 3) & 3;
    int hcol = ((n >> 6) << 4) | (((n >> 5) & 1) << 3) | (n & 7);
    int col  = gate * HH + hcol;
    int kg   = kt * 32 + kb * 16 + r * 8 + (lane & 3) * 2;
    float v0 = (kg < II)     ? Wx[(long)kg * NG + col]       : Wh[(long)(kg - II) * NG + col];
    float v1 = (kg + 1 < II) ? Wx[(long)(kg + 1) * NG + col] : Wh[(long)(kg + 1 - II) * NG + col];
    __half2 v = __floats2half2_rn(v0, v1);
    g_Wp[p] = *(uint32_t*)&v;
}

__global__ void init_state(const float* __restrict__ h0, const float* __restrict__ c0) {
    uint32_t p = blockIdx.x * blockDim.x + threadIdx.x;
    if (p < 2) g_bar[p] = 0u;
    if (p >= 262144) return;
    if (p < 131072) {   // h0 -> packed A images
        int j    = p & 3;
        int lane = (p >> 2) & 31;
        int kb   = (p >> 7) & 1;
        int mb   = (p >> 8) & 7;
        int hkt  = (p >> 11) & 31;
        int mt   = (p >> 16) & 1;
        int rowp = (lane >> 2) + 8 * (j & 1);
        int kp   = (lane & 3) * 2 + 8 * (j >> 1);
        int b    = mt * 128 + mb * 16 + rowp;
        int hc   = hkt * 32 + kb * 16 + kp;
        __half2 v = __floats2half2_rn(h0[b * HH + hc], h0[b * HH + hc + 1]);
        g_hp[0][p] = *(uint32_t*)&v;
    }
    g_c[p] = c0[p];
}

// ---------------------------------------------------------------------------
__device__ __forceinline__ void cp16(uint32_t saddr, const void* g) {
    asm volatile("cp.async.cg.shared.global [%0], [%1], 16;\n" :: "r"(saddr), "l"(g));
}
#define CP_COMMIT() asm volatile("cp.async.commit_group;\n" ::: "memory")
#define CP_WAIT(N)  asm volatile("cp.async.wait_group %0;\n" :: "n"(N) : "memory")

__device__ __forceinline__ void bar_arrive(unsigned* a) {
    asm volatile("red.release.gpu.global.add.u32 [%0], 1;" :: "l"(a) : "memory");
}
__device__ __forceinline__ unsigned bar_poll(const unsigned* a) {
    unsigned v;
    asm volatile("ld.acquire.gpu.global.u32 %0, [%1];" : "=r"(v) : "l"(a) : "memory");
    return v;
}

__device__ __forceinline__ void mma16816(float* d, const uint4& a, uint32_t b0, uint32_t b1) {
    asm volatile(
        "mma.sync.aligned.m16n8k16.row.col.f32.f16.f16.f32 "
        "{%0,%1,%2,%3}, {%4,%5,%6,%7}, {%8,%9}, {%0,%1,%2,%3};"
        : "+f"(d[0]), "+f"(d[1]), "+f"(d[2]), "+f"(d[3])
        : "r"(a.x), "r"(a.y), "r"(a.z), "r"(a.w), "r"(b0), "r"(b1));
}

// ---------------------------------------------------------------------------
// Persistent kernel: all 256 timesteps, per-mtile barriers hidden behind the
// x-only prologue stages.
// ---------------------------------------------------------------------------
__global__ void __launch_bounds__(256, 1)
lstm_persist(const float* __restrict__ bias,   // (4H,)
             float* __restrict__ out)          // outputs | hN | cN
{
    extern __shared__ uint4 smem[];
    uint4* sA4 = smem;                      // [5][1024] uint4
    uint4* sB4 = smem + STAGES * 1024;      // [5][512]  uint4

    const int tid    = threadIdx.x;
    const int lane   = tid & 31;
    const int warp   = tid >> 5;
    const int warp_m = warp >> 1;        // 0..3 (32 rows)
    const int warp_n = warp & 1;         // 0..1 (32 cols)
    const int ctan   = blockIdx.x;       // 0..63
    const int mt     = blockIdx.y;       // 0..1

    const uint32_t sA_b = (uint32_t)__cvta_generic_to_shared(sA4);
    const uint32_t sB_b = (uint32_t)__cvta_generic_to_shared(sB4);

    const int hbase = ctan * 16 + warp_n * 8 + 2 * (lane & 3);

    float bg0[4], bg1[4];
    #pragma unroll
    for (int g = 0; g < 4; g++) {
        bg0[g] = __ldg(bias + g * HH + hbase);
        bg1[g] = __ldg(bias + g * HH + hbase + 1);
    }

    unsigned* mybar = &g_bar[mt];

    for (int t = 0; t < TT; t++) {
        const int srcbuf = t & 1;
        const uint32_t* __restrict__ hsrc = g_hp[srcbuf];
        uint32_t*       __restrict__ hdst = g_hp[srcbuf ^ 1];

        float acc[2][4][4];
        #pragma unroll
        for (int g = 0; g < 4; g++) {
            #pragma unroll
            for (int mb = 0; mb < 2; mb++) {
                acc[mb][g][0] = bg0[g]; acc[mb][g][1] = bg1[g];
                acc[mb][g][2] = bg0[g]; acc[mb][g][3] = bg1[g];
            }
        }

        auto issue = [&](int st) {
            int s = st % STAGES;
            const uint32_t* asrc = (st < XST)
                ? g_xp + ((long)(t * 2 + mt) * XKT + st * 2) * A_IMG
                : hsrc + (long)(mt * 32 + (st - XST) * 2) * A_IMG;
            const uint32_t* bsrc = g_Wp + ((long)ctan * NKT + st * 2) * B_IMG;
            #pragma unroll
            for (int r = 0; r < 4; r++) {
                int idx = tid + 256 * r;
                cp16(sA_b + (uint32_t)(s * 1024 + idx) * 16, asrc + idx * 4);
            }
            #pragma unroll
            for (int r = 0; r < 2; r++) {
                int idx = tid + 256 * r;
                cp16(sB_b + (uint32_t)(s * 512 + idx) * 16, bsrc + idx * 4);
            }
        };

        // x-only prologue (stages 0..3 touch g_xp/g_Wp only) — overlaps the spin
        issue(0); CP_COMMIT();
        issue(1); CP_COMMIT();
        issue(2); CP_COMMIT();
        issue(3); CP_COMMIT();

        // wait for all mt-peers to publish h(t) before any h stage is issued
        if (t > 0) {
            if (tid == 0) {
                unsigned target = (unsigned)(64 * t);
                while (bar_poll(mybar) < target) { }
            }
            __syncthreads();
        }

        for (int st = 0; st < NST; st++) {
            CP_WAIT(3);
            __syncthreads();

            int s = st % STAGES;
            const uint4* A  = sA4 + s * 1024;
            const uint4* Bm = sB4 + s * 512;

            #pragma unroll
            for (int kk = 0; kk < 4; kk++) {
                uint4 af0 = A[(kk >> 1) * 512 + ((warp_m * 2 + 0) * 2 + (kk & 1)) * 32 + lane];
                uint4 af1 = A[(kk >> 1) * 512 + ((warp_m * 2 + 1) * 2 + (kk & 1)) * 32 + lane];
                uint4 bf0 = Bm[(kk >> 1) * 256 + ((warp_n * 2 + 0) * 2 + (kk & 1)) * 32 + lane];
                uint4 bf1 = Bm[(kk >> 1) * 256 + ((warp_n * 2 + 1) * 2 + (kk & 1)) * 32 + lane];
                mma16816(acc[0][0], af0, bf0.x, bf0.y);
                mma16816(acc[0][1], af0, bf0.z, bf0.w);
                mma16816(acc[0][2], af0, bf1.x, bf1.y);
                mma16816(acc[0][3], af0, bf1.z, bf1.w);
                mma16816(acc[1][0], af1, bf0.x, bf0.y);
                mma16816(acc[1][1], af1, bf0.z, bf0.w);
                mma16816(acc[1][2], af1, bf1.x, bf1.y);
                mma16816(acc[1][3], af1, bf1.z, bf1.w);
            }

            if (st + 4 < NST) issue(st + 4);
            CP_COMMIT();
        }

        // ---- epilogue -------------------------------------------------------
        #pragma unroll
        for (int mb = 0; mb < 2; mb++) {
            #pragma unroll
            for (int half = 0; half < 2; half++) {
                int m_loc = warp_m * 32 + mb * 16 + (lane >> 2) + half * 8;
                int r = mt * 128 + m_loc;
                long cidx = (long)r * HH + hbase;
                float2 cold = *(const float2*)(g_c + cidx);
                float hn[2], cn[2];
                #pragma unroll
                for (int j = 0; j < 2; j++) {
                    int c2 = half * 2 + j;
                    float ii = sig_fast(acc[mb][0][c2]);
                    float ff = sig_fast(acc[mb][1][c2]);
                    float tg = tanh_fast(acc[mb][2][c2]);
                    float oo = sig_fast(acc[mb][3][c2]);
                    float cnew = ff * (j ? cold.y : cold.x) + ii * tg;
                    cn[j] = cnew;
                    hn[j] = oo * tanh_fast(cnew);
                }
                *(float2*)(g_c + cidx) = make_float2(cn[0], cn[1]);
                *(float2*)(out + ((long)r * TT + t) * HH + hbase) = make_float2(hn[0], hn[1]);
                if (t == TT - 1) {
                    *(float2*)(out + BTH + (long)r * HH + hbase)      = make_float2(hn[0], hn[1]);
                    *(float2*)(out + BTH + BH + (long)r * HH + hbase) = make_float2(cn[0], cn[1]);
                }
                float h0s = hn[0], h1s = hn[1];
                if (hbase == 0) {
                    h0s = hn[0] + TAUc * (MHUc * hn[0] + hn[1] / MHUc);
                    h1s = hn[1] - TAUc * (MHUc * hn[0]);
                }
                int mbb  = m_loc >> 4;
                int rowp = m_loc & 15;
                int hkt  = hbase >> 5;
                int kb   = (hbase >> 4) & 1;
                int jj   = ((rowp >> 3) & 1) | ((((hbase & 15) >= 8) ? 1 : 0) << 1);
                int lanep = ((rowp & 7) << 2) | ((hbase & 7) >> 1);
                __half2 hv = __floats2half2_rn(h0s, h1s);
                hdst[(long)(mt * 32 + hkt) * A_IMG + ((mbb * 2 + kb) * 32 + lanep) * 4 + jj] =
                    *(uint32_t*)&hv;
            }
        }

        // publish h(t+1 inputs): CTA-wide order via bar, release via red.release
        if (t + 1 < TT) {
            __syncthreads();
            if (tid == 0) bar_arrive(mybar);
        }
    }
}

// ---------------------------------------------------------------------------
extern "C" void kernel_launch(void* const* d_in, const int* in_sizes, int n_in,
                              void* d_out, int out_size) {
    const float* x  = (const float*)d_in[0];
    const float* h0 = (const float*)d_in[1];
    const float* c0 = (const float*)d_in[2];
    const float* Wx = (const float*)d_in[3];
    const float* Wh = (const float*)d_in[4];
    const float* b  = (const float*)d_in[5];
    float* out = (float*)d_out;

    cudaFuncSetAttribute(lstm_persist, cudaFuncAttributeMaxDynamicSharedMemorySize, DSMEM);

    transform_x<<<32768, 256>>>(x);
    {
        long total = (long)64 * NKT * B_IMG;
        transform_W<<<(int)((total + 255) / 256), 256>>>(Wx, Wh);
    }
    init_state<<<1024, 256>>>(h0, c0);

    lstm_persist<<<dim3(64, 2), 256, DSMEM>>>(b, out);
}

// round 11
// speedup vs baseline: 1.3392x; 1.0923x over previous
#include <cuda_runtime.h>
#include <cuda_fp16.h>
#include <math.h>
#include <stdint.h>

// Problem constants
#define BB   256
#define TT   256
#define II   256
#define HH   1024
#define KTOT 1280
#define NG   4096
#define TAUc 0.05f
#define MHUc 1.5f
#define BTH  ((long)BB * TT * HH)
#define BH   ((long)BB * HH)

// Tiling: BM=128, BN=64, stage BK=128 (8 x k16). Grid (64 ctan, 2 mtile) = 128 CTAs,
// persistent (1/SM). 256 threads = 8 warps, 4m x 2n, warp tile 32x32.
#define NKT    40          // 32-k images (KTOT/32)
#define XKT    8           // x images per (t, mt)
#define NST    10          // stages per step (KTOT/128)
#define XST    2           // x stages
#define STAGES 4           // smem ring slots
#define A_IMG  2048        // uint32 per 32-k A image (128 rows x 32 k fp16)
#define B_IMG  1024        // uint32 per 32-k B image (64 n x 32 k fp16)
// slot: A 2048 uint4 (32KB) + B 1024 uint4 (16KB) = 48KB
#define DSMEM  (STAGES * 3072 * 16)   // 192KB dynamic smem

// ---------------------------------------------------------------------------
// Persistent scratch: operand images stored exactly as smem stages should look
// (mma-fragment register images, fp16) -> per-step copies are pure linear.
// A image: [mb(8)][kb16(2)][lane(32)][reg(4)] uint32 (128 rows x 32 k):
//   reg j, half h: row' = (lane>>2) + 8*(j&1), k' = (lane&3)*2 + 8*(j>>1) + h
// B image: [nbp(4)][kb16(2)][lane(32)][j(4)] uint32:
//   nb = nbp*2 + (j>>1), r = j&1: k = r*8 + (lane&3)*2 + h, n = nb*8 + (lane>>2)
// ---------------------------------------------------------------------------
__device__ uint32_t g_xp[(long)TT * 2 * XKT * A_IMG];
__device__ uint32_t g_hp[2][2 * 32 * A_IMG];
__device__ uint32_t g_Wp[(long)64 * NKT * B_IMG];
__device__ float    g_c[BB * HH];
__device__ unsigned g_bar[2];              // per-mtile phase barriers (monotonic)

__device__ __forceinline__ float tanh_fast(float x) {
    float r;
    asm("tanh.approx.f32 %0, %1;" : "=f"(r) : "f"(x));
    return r;
}
__device__ __forceinline__ float sig_fast(float x) {
    return 0.5f * tanh_fast(0.5f * x) + 0.5f;
}

// ---------------------------------------------------------------------------
// Column permutation: permuted col n -> gate = (n>>3)&3,
//   hcol = ((n>>6)<<4) | (((n>>5)&1)<<3) | (n&7)
// ---------------------------------------------------------------------------
__global__ void transform_x(const float* __restrict__ x) {
    uint32_t p = blockIdx.x * blockDim.x + threadIdx.x;   // 8,388,608 total
    int j    = p & 3;
    int lane = (p >> 2) & 31;
    int kb   = (p >> 7) & 1;
    int mb   = (p >> 8) & 7;
    int kt   = (p >> 11) & 7;
    int mt   = (p >> 14) & 1;
    int t    = p >> 15;
    int rowp = (lane >> 2) + 8 * (j & 1);
    int kp   = (lane & 3) * 2 + 8 * (j >> 1);
    int b    = mt * 128 + mb * 16 + rowp;
    int i    = kt * 32 + kb * 16 + kp;
    const float* src = x + ((long)b * TT + t) * II + i;
    __half2 v = __floats2half2_rn(src[0], src[1]);
    g_xp[p] = *(uint32_t*)&v;
}

__global__ void transform_W(const float* __restrict__ Wx, const float* __restrict__ Wh) {
    uint32_t p = blockIdx.x * blockDim.x + threadIdx.x;
    if (p >= (uint32_t)64 * NKT * B_IMG) return;
    int j    = p & 3;
    int lane = (p >> 2) & 31;
    int kb   = (p >> 7) & 1;
    int nbp  = (p >> 8) & 3;
    int kt   = (int)((p >> 10) % NKT);
    int ctan = (int)((p >> 10) / NKT);
    int nb   = nbp * 2 + (j >> 1);
    int r    = j & 1;
    int n    = ctan * 64 + nb * 8 + (lane >> 2);
    int gate = (n >> 3) & 3;
    int hcol = ((n >> 6) << 4) | (((n >> 5) & 1) << 3) | (n & 7);
    int col  = gate * HH + hcol;
    int kg   = kt * 32 + kb * 16 + r * 8 + (lane & 3) * 2;
    float v0 = (kg < II)     ? Wx[(long)kg * NG + col]       : Wh[(long)(kg - II) * NG + col];
    float v1 = (kg + 1 < II) ? Wx[(long)(kg + 1) * NG + col] : Wh[(long)(kg + 1 - II) * NG + col];
    __half2 v = __floats2half2_rn(v0, v1);
    g_Wp[p] = *(uint32_t*)&v;
}

__global__ void init_state(const float* __restrict__ h0, const float* __restrict__ c0) {
    uint32_t p = blockIdx.x * blockDim.x + threadIdx.x;
    if (p < 2) g_bar[p] = 0u;
    if (p >= 262144) return;
    if (p < 131072) {   // h0 -> packed A images
        int j    = p & 3;
        int lane = (p >> 2) & 31;
        int kb   = (p >> 7) & 1;
        int mb   = (p >> 8) & 7;
        int hkt  = (p >> 11) & 31;
        int mt   = (p >> 16) & 1;
        int rowp = (lane >> 2) + 8 * (j & 1);
        int kp   = (lane & 3) * 2 + 8 * (j >> 1);
        int b    = mt * 128 + mb * 16 + rowp;
        int hc   = hkt * 32 + kb * 16 + kp;
        __half2 v = __floats2half2_rn(h0[b * HH + hc], h0[b * HH + hc + 1]);
        g_hp[0][p] = *(uint32_t*)&v;
    }
    g_c[p] = c0[p];
}

// ---------------------------------------------------------------------------
__device__ __forceinline__ void cp16(uint32_t saddr, const void* g) {
    asm volatile("cp.async.cg.shared.global [%0], [%1], 16;\n" :: "r"(saddr), "l"(g));
}
#define CP_COMMIT() asm volatile("cp.async.commit_group;\n" ::: "memory")
#define CP_WAIT(N)  asm volatile("cp.async.wait_group %0;\n" :: "n"(N) : "memory")

__device__ __forceinline__ void bar_arrive(unsigned* a) {
    asm volatile("red.release.gpu.global.add.u32 [%0], 1;" :: "l"(a) : "memory");
}
__device__ __forceinline__ unsigned bar_poll(const unsigned* a) {
    unsigned v;
    asm volatile("ld.acquire.gpu.global.u32 %0, [%1];" : "=r"(v) : "l"(a) : "memory");
    return v;
}

__device__ __forceinline__ void mma16816(float* d, const uint4& a, uint32_t b0, uint32_t b1) {
    asm volatile(
        "mma.sync.aligned.m16n8k16.row.col.f32.f16.f16.f32 "
        "{%0,%1,%2,%3}, {%4,%5,%6,%7}, {%8,%9}, {%0,%1,%2,%3};"
        : "+f"(d[0]), "+f"(d[1]), "+f"(d[2]), "+f"(d[3])
        : "r"(a.x), "r"(a.y), "r"(a.z), "r"(a.w), "r"(b0), "r"(b1));
}

// ---------------------------------------------------------------------------
// Persistent kernel: all 256 timesteps; 10 BK=128 stages per step; per-mtile
// barriers hidden behind the 2 x-only prologue stages.
// ---------------------------------------------------------------------------
__global__ void __launch_bounds__(256, 1)
lstm_persist(const float* __restrict__ bias,   // (4H,)
             float* __restrict__ out)          // outputs | hN | cN
{
    extern __shared__ uint4 smem[];
    uint4* sA4 = smem;                      // [4][2048] uint4
    uint4* sB4 = smem + STAGES * 2048;      // [4][1024] uint4

    const int tid    = threadIdx.x;
    const int lane   = tid & 31;
    const int warp   = tid >> 5;
    const int warp_m = warp >> 1;        // 0..3 (32 rows)
    const int warp_n = warp & 1;         // 0..1 (32 cols)
    const int ctan   = blockIdx.x;       // 0..63
    const int mt     = blockIdx.y;       // 0..1

    const uint32_t sA_b = (uint32_t)__cvta_generic_to_shared(sA4);
    const uint32_t sB_b = (uint32_t)__cvta_generic_to_shared(sB4);

    const int hbase = ctan * 16 + warp_n * 8 + 2 * (lane & 3);

    float bg0[4], bg1[4];
    #pragma unroll
    for (int g = 0; g < 4; g++) {
        bg0[g] = __ldg(bias + g * HH + hbase);
        bg1[g] = __ldg(bias + g * HH + hbase + 1);
    }

    unsigned* mybar = &g_bar[mt];

    for (int t = 0; t < TT; t++) {
        const int srcbuf = t & 1;
        const uint32_t* __restrict__ hsrc = g_hp[srcbuf];
        uint32_t*       __restrict__ hdst = g_hp[srcbuf ^ 1];

        float acc[2][4][4];
        #pragma unroll
        for (int g = 0; g < 4; g++) {
            #pragma unroll
            for (int mb = 0; mb < 2; mb++) {
                acc[mb][g][0] = bg0[g]; acc[mb][g][1] = bg1[g];
                acc[mb][g][2] = bg0[g]; acc[mb][g][3] = bg1[g];
            }
        }

        // BK=128 stage: 4 consecutive 32-k images for A and B
        auto issue = [&](int st) {
            int s = st & (STAGES - 1);
            const uint32_t* asrc = (st < XST)
                ? g_xp + ((long)(t * 2 + mt) * XKT + st * 4) * A_IMG
                : hsrc + (long)(mt * 32 + (st - XST) * 4) * A_IMG;
            const uint32_t* bsrc = g_Wp + ((long)ctan * NKT + st * 4) * B_IMG;
            #pragma unroll
            for (int r = 0; r < 8; r++) {
                int idx = tid + 256 * r;
                cp16(sA_b + (uint32_t)(s * 2048 + idx) * 16, asrc + idx * 4);
            }
            #pragma unroll
            for (int r = 0; r < 4; r++) {
                int idx = tid + 256 * r;
                cp16(sB_b + (uint32_t)(s * 1024 + idx) * 16, bsrc + idx * 4);
            }
        };

        // x-only prologue (stages 0,1) — overlaps the barrier spin
        issue(0); CP_COMMIT();
        issue(1); CP_COMMIT();

        // wait for all mt-peers to publish h(t)
        if (t > 0) {
            if (tid == 0) {
                unsigned target = (unsigned)(64 * t);
                while (bar_poll(mybar) < target) { }
            }
            __syncthreads();
        }
        issue(2); CP_COMMIT();

        for (int st = 0; st < NST; st++) {
            CP_WAIT(2);
            __syncthreads();

            int s = st & (STAGES - 1);
            const uint4* A  = sA4 + s * 2048;
            const uint4* Bm = sB4 + s * 1024;

            #pragma unroll
            for (int kk = 0; kk < 8; kk++) {   // 8 k16 chunks per stage
                uint4 af0 = A[(kk >> 1) * 512 + ((warp_m * 2 + 0) * 2 + (kk & 1)) * 32 + lane];
                uint4 af1 = A[(kk >> 1) * 512 + ((warp_m * 2 + 1) * 2 + (kk & 1)) * 32 + lane];
                uint4 bf0 = Bm[(kk >> 1) * 256 + ((warp_n * 2 + 0) * 2 + (kk & 1)) * 32 + lane];
                uint4 bf1 = Bm[(kk >> 1) * 256 + ((warp_n * 2 + 1) * 2 + (kk & 1)) * 32 + lane];
                mma16816(acc[0][0], af0, bf0.x, bf0.y);
                mma16816(acc[0][1], af0, bf0.z, bf0.w);
                mma16816(acc[0][2], af0, bf1.x, bf1.y);
                mma16816(acc[0][3], af0, bf1.z, bf1.w);
                mma16816(acc[1][0], af1, bf0.x, bf0.y);
                mma16816(acc[1][1], af1, bf0.z, bf0.w);
                mma16816(acc[1][2], af1, bf1.x, bf1.y);
                mma16816(acc[1][3], af1, bf1.z, bf1.w);
            }

            if (st + 3 < NST) issue(st + 3);   // slot (st-1)&3: readers passed barrier above
            CP_COMMIT();
        }

        // ---- epilogue -------------------------------------------------------
        #pragma unroll
        for (int mb = 0; mb < 2; mb++) {
            #pragma unroll
            for (int half = 0; half < 2; half++) {
                int m_loc = warp_m * 32 + mb * 16 + (lane >> 2) + half * 8;
                int r = mt * 128 + m_loc;
                long cidx = (long)r * HH + hbase;
                float2 cold = *(const float2*)(g_c + cidx);
                float hn[2], cn[2];
                #pragma unroll
                for (int j = 0; j < 2; j++) {
                    int c2 = half * 2 + j;
                    float ii = sig_fast(acc[mb][0][c2]);
                    float ff = sig_fast(acc[mb][1][c2]);
                    float tg = tanh_fast(acc[mb][2][c2]);
                    float oo = sig_fast(acc[mb][3][c2]);
                    float cnew = ff * (j ? cold.y : cold.x) + ii * tg;
                    cn[j] = cnew;
                    hn[j] = oo * tanh_fast(cnew);
                }
                *(float2*)(g_c + cidx) = make_float2(cn[0], cn[1]);
                *(float2*)(out + ((long)r * TT + t) * HH + hbase) = make_float2(hn[0], hn[1]);
                if (t == TT - 1) {
                    *(float2*)(out + BTH + (long)r * HH + hbase)      = make_float2(hn[0], hn[1]);
                    *(float2*)(out + BTH + BH + (long)r * HH + hbase) = make_float2(cn[0], cn[1]);
                }
                float h0s = hn[0], h1s = hn[1];
                if (hbase == 0) {
                    h0s = hn[0] + TAUc * (MHUc * hn[0] + hn[1] / MHUc);
                    h1s = hn[1] - TAUc * (MHUc * hn[0]);
                }
                int mbb  = m_loc >> 4;
                int rowp = m_loc & 15;
                int hkt  = hbase >> 5;
                int kb   = (hbase >> 4) & 1;
                int jj   = ((rowp >> 3) & 1) | ((((hbase & 15) >= 8) ? 1 : 0) << 1);
                int lanep = ((rowp & 7) << 2) | ((hbase & 7) >> 1);
                __half2 hv = __floats2half2_rn(h0s, h1s);
                hdst[(long)(mt * 32 + hkt) * A_IMG + ((mbb * 2 + kb) * 32 + lanep) * 4 + jj] =
                    *(uint32_t*)&hv;
            }
        }

        if (t + 1 < TT) {
            __syncthreads();
            if (tid == 0) bar_arrive(mybar);
        }
    }
}

// ---------------------------------------------------------------------------
extern "C" void kernel_launch(void* const* d_in, const int* in_sizes, int n_in,
                              void* d_out, int out_size) {
    const float* x  = (const float*)d_in[0];
    const float* h0 = (const float*)d_in[1];
    const float* c0 = (const float*)d_in[2];
    const float* Wx = (const float*)d_in[3];
    const float* Wh = (const float*)d_in[4];
    const float* b  = (const float*)d_in[5];
    float* out = (float*)d_out;

    cudaFuncSetAttribute(lstm_persist, cudaFuncAttributeMaxDynamicSharedMemorySize, DSMEM);

    transform_x<<<32768, 256>>>(x);
    {
        long total = (long)64 * NKT * B_IMG;
        transform_W<<<(int)((total + 255) / 256), 256>>>(Wx, Wh);
    }
    init_state<<<1024, 256>>>(h0, c0);

    lstm_persist<<<dim3(64, 2), 256, DSMEM>>>(b, out);
}